// round 4
// baseline (speedup 1.0000x reference)
#include <cuda_runtime.h>
#include <math.h>
#include <stdint.h>

#define B_    2
#define N_    1024
#define D_    1024
#define H_    16
#define DH_   64
#define MLP_  4096
#define DEPTH_ 6
#define M_    (B_ * N_)   /* 2048 rows */

// ---------------- scratch -----------------------------------------------
__device__ float g_h   [(size_t)M_ * D_];
__device__ float g_qkv [(size_t)M_ * 3 * D_];
__device__ float g_o   [(size_t)M_ * D_];
__device__ float g_mlp [(size_t)M_ * MLP_];

// ---------------- tf32 / async helpers ------------------------------------
__device__ __forceinline__ float f2tf(float x) {
    uint32_t u; asm("cvt.rna.tf32.f32 %0, %1;" : "=r"(u) : "f"(x));
    return __uint_as_float(u);
}
__device__ __forceinline__ void mma8(float* d, const float* a, const float* b) {
    asm volatile(
        "mma.sync.aligned.m16n8k8.row.col.f32.tf32.tf32.f32 "
        "{%0,%1,%2,%3},{%4,%5,%6,%7},{%8,%9},{%0,%1,%2,%3};"
        : "+f"(d[0]), "+f"(d[1]), "+f"(d[2]), "+f"(d[3])
        : "r"(__float_as_uint(a[0])), "r"(__float_as_uint(a[1])),
          "r"(__float_as_uint(a[2])), "r"(__float_as_uint(a[3])),
          "r"(__float_as_uint(b[0])), "r"(__float_as_uint(b[1])));
}
__device__ __forceinline__ void cp16(void* smem_dst, const void* gmem_src) {
    uint32_t dst = (uint32_t)__cvta_generic_to_shared(smem_dst);
    asm volatile("cp.async.cg.shared.global [%0], [%1], 16;"
                 :: "r"(dst), "l"(gmem_src));
}
__device__ __forceinline__ void cp_commit() {
    asm volatile("cp.async.commit_group;");
}

// ---------------- LayerNorm ----------------------------------------------
__global__ void __launch_bounds__(256) ln_kernel(
    const float* __restrict__ x, const float* __restrict__ s,
    const float* __restrict__ b, float* __restrict__ o)
{
    __shared__ float red[2][8];
    int row = blockIdx.x;
    const float* xr = x + (size_t)row * D_;
    float* orow = o + (size_t)row * D_;
    int t = threadIdx.x;
    float v[4];
    float sum = 0.f, sq = 0.f;
#pragma unroll
    for (int i = 0; i < 4; i++) {
        float z = xr[t + i * 256];
        v[i] = z; sum += z; sq += z * z;
    }
#pragma unroll
    for (int off = 16; off > 0; off >>= 1) {
        sum += __shfl_xor_sync(0xffffffffu, sum, off);
        sq  += __shfl_xor_sync(0xffffffffu, sq,  off);
    }
    if ((t & 31) == 0) { red[0][t >> 5] = sum; red[1][t >> 5] = sq; }
    __syncthreads();
    sum = 0.f; sq = 0.f;
#pragma unroll
    for (int i = 0; i < 8; i++) { sum += red[0][i]; sq += red[1][i]; }
    float mean = sum * (1.f / D_);
    float var  = sq  * (1.f / D_) - mean * mean;
    float rstd = rsqrtf(var + 1e-5f);
#pragma unroll
    for (int i = 0; i < 4; i++) {
        int c = t + i * 256;
        orow[c] = (v[i] - mean) * rstd * s[c] + b[c];
    }
}

// ---------------- tf32 tensor-core GEMM, cp.async double-buffered ----------
template<int BN, int WM, int WN, int EPI>
__global__ void __launch_bounds__(256, 1) gemm_tc(
    const float* __restrict__ A, const float* __restrict__ W,
    const float* __restrict__ bias, const float* __restrict__ res,
    float* __restrict__ C, int M, int N, int K)
{
    const int BNP = BN + 4;
    const int MI = WM / 16, NI = WN / 8;
    const int WARPS_N = BN / WN;

    extern __shared__ float sm[];
    float (*As)[128][36] = reinterpret_cast<float(*)[128][36]>(sm);
    float (*Bs)[32][BNP] = reinterpret_cast<float(*)[32][BNP]>(sm + 2 * 128 * 36);

    int tid = threadIdx.x;
    int bx = blockIdx.x, by = blockIdx.y;
    int w = tid >> 5, lane = tid & 31;
    int wn = w % WARPS_N, wm = w / WARPS_N;
    int g = lane >> 2, q = lane & 3;

    const float* Ab = A + (size_t)by * 128 * K;
    const float* Wb = W + (size_t)bx * BN;
    int KT = K / 32;

    float acc[MI][NI][4];
#pragma unroll
    for (int mi = 0; mi < MI; mi++)
#pragma unroll
        for (int ni = 0; ni < NI; ni++)
#pragma unroll
            for (int k = 0; k < 4; k++) acc[mi][ni][k] = 0.f;

    auto load_tile = [&](int kt, int s) {
        int k0 = kt * 32;
#pragma unroll
        for (int i = 0; i < 4; i++) {
            int idx = tid + i * 256;
            int r = idx >> 3, c4 = (idx & 7) * 4;
            cp16(&As[s][r][c4], Ab + (size_t)r * K + k0 + c4);
        }
#pragma unroll
        for (int i = 0; i < BN / 32; i++) {
            int idx = tid + i * 256;
            int r = idx / (BN / 4), c4 = (idx % (BN / 4)) * 4;
            cp16(&Bs[s][r][c4], Wb + (size_t)(k0 + r) * N + c4);
        }
        cp_commit();
    };

    load_tile(0, 0);

    for (int kt = 0; kt < KT; kt++) {
        int s = kt & 1;
        if (kt + 1 < KT) {
            load_tile(kt + 1, (kt + 1) & 1);
            asm volatile("cp.async.wait_group 1;");
        } else {
            asm volatile("cp.async.wait_group 0;");
        }
        __syncthreads();
#pragma unroll
        for (int ks = 0; ks < 4; ks++) {
            int kb = ks * 8;
            float a[MI][4];
#pragma unroll
            for (int mi = 0; mi < MI; mi++) {
                int m = wm * WM + mi * 16;
                a[mi][0] = f2tf(As[s][m + g    ][kb + q]);
                a[mi][1] = f2tf(As[s][m + g + 8][kb + q]);
                a[mi][2] = f2tf(As[s][m + g    ][kb + q + 4]);
                a[mi][3] = f2tf(As[s][m + g + 8][kb + q + 4]);
            }
            float b[NI][2];
#pragma unroll
            for (int ni = 0; ni < NI; ni++) {
                int n = wn * WN + ni * 8 + g;
                b[ni][0] = f2tf(Bs[s][kb + q    ][n]);
                b[ni][1] = f2tf(Bs[s][kb + q + 4][n]);
            }
#pragma unroll
            for (int mi = 0; mi < MI; mi++)
#pragma unroll
                for (int ni = 0; ni < NI; ni++) mma8(acc[mi][ni], a[mi], b[ni]);
        }
        __syncthreads();
    }

#pragma unroll
    for (int mi = 0; mi < MI; mi++) {
        int r0 = by * 128 + wm * WM + mi * 16 + g;
#pragma unroll
        for (int ni = 0; ni < NI; ni++) {
            int c = bx * BN + wn * WN + ni * 8 + q * 2;
            float2 v0 = make_float2(acc[mi][ni][0], acc[mi][ni][1]);
            float2 v1 = make_float2(acc[mi][ni][2], acc[mi][ni][3]);
            if (EPI & 1) {
                float b0 = bias[c], b1 = bias[c + 1];
                v0.x += b0; v0.y += b1; v1.x += b0; v1.y += b1;
            }
            if (EPI & 2) {
                const float is2 = 0.70710678118654752f;
                v0.x = 0.5f * v0.x * (1.f + erff(v0.x * is2));
                v0.y = 0.5f * v0.y * (1.f + erff(v0.y * is2));
                v1.x = 0.5f * v1.x * (1.f + erff(v1.x * is2));
                v1.y = 0.5f * v1.y * (1.f + erff(v1.y * is2));
            }
            size_t a0 = (size_t)r0 * N + c;
            size_t a1 = (size_t)(r0 + 8) * N + c;
            if (EPI & 4) {
                float2 r0v = *(const float2*)(res + a0);
                float2 r1v = *(const float2*)(res + a1);
                v0.x += r0v.x; v0.y += r0v.y; v1.x += r1v.x; v1.y += r1v.y;
            }
            *(float2*)(C + a0) = v0;
            *(float2*)(C + a1) = v1;
        }
    }
}

// ---------------- fused flash attention ------------------------------------
// grid (N/128 = 8, B*H = 32), 256 threads = 8 warps, each warp owns 16 q-rows.
// Q tile 128x64 resident; KV chunks of 64 double-buffered via cp.async.
// Online softmax fully warp-local; P staged via warp-private smem slab.
#define FQ_OFF  0
#define FK_OFF  (128 * 68)                 /* 2 x 64 x 68 */
#define FV_OFF  (FK_OFF + 2 * 64 * 68)
#define FP_OFF  (FV_OFF + 2 * 64 * 68)
#define FSMEM   ((FP_OFF + 128 * 68) * 4)  /* 139,264 bytes */

__global__ void __launch_bounds__(256, 1) flash_tc(
    const float* __restrict__ qkv, float* __restrict__ o)
{
    extern __shared__ float fsm[];
    float (*Qs)[68] = reinterpret_cast<float(*)[68]>(fsm + FQ_OFF);
    float (*Ks)[64][68] = reinterpret_cast<float(*)[64][68]>(fsm + FK_OFF);
    float (*Vs)[64][68] = reinterpret_cast<float(*)[64][68]>(fsm + FV_OFF);
    float (*Ps)[68] = reinterpret_cast<float(*)[68]>(fsm + FP_OFF);

    int bh = blockIdx.y;
    int b = bh >> 4, h = bh & 15;
    int i0 = blockIdx.x * 128;
    const float* Qb = qkv + (size_t)b * N_ * 3 * D_ + (size_t)h * DH_;
    const float* Kb = Qb + D_;
    const float* Vb = Qb + 2 * D_;

    int tid = threadIdx.x;
    int w = tid >> 5, lane = tid & 31;
    int g = lane >> 2, q = lane & 3;
    int m0 = w * 16;

    // load Q tile (pre-converted to tf32)
#pragma unroll
    for (int i = 0; i < 8; i++) {
        int idx = tid + i * 256;
        int r = idx >> 4, c4 = (idx & 15) * 4;
        float4 f = *(const float4*)(Qb + (size_t)(i0 + r) * 3 * D_ + c4);
        f.x = f2tf(f.x); f.y = f2tf(f.y); f.z = f2tf(f.z); f.w = f2tf(f.w);
        *(float4*)&Qs[r][c4] = f;
    }

    auto load_kv = [&](int kt, int s) {
        int j0 = kt * 64;
#pragma unroll
        for (int i = 0; i < 4; i++) {
            int idx = tid + i * 256;
            int r = idx >> 4, c4 = (idx & 15) * 4;
            cp16(&Ks[s][r][c4], Kb + (size_t)(j0 + r) * 3 * D_ + c4);
            cp16(&Vs[s][r][c4], Vb + (size_t)(j0 + r) * 3 * D_ + c4);
        }
        cp_commit();
    };

    float oacc[8][4];
#pragma unroll
    for (int di = 0; di < 8; di++)
#pragma unroll
        for (int k = 0; k < 4; k++) oacc[di][k] = 0.f;
    float mrow0 = -1e30f, mrow1 = -1e30f, lrow0 = 0.f, lrow1 = 0.f;

    load_kv(0, 0);

    const float scale = 0.03125f;   // D^-0.5 (full-dim per reference)

    for (int kt = 0; kt < 16; kt++) {
        int s = kt & 1;
        if (kt + 1 < 16) {
            load_kv(kt + 1, (kt + 1) & 1);
            asm volatile("cp.async.wait_group 1;");
        } else {
            asm volatile("cp.async.wait_group 0;");
        }
        __syncthreads();

        // ---- S = Q K^T (128x64 per CTA; this warp: 16x64) ----
        float sacc[8][4];
#pragma unroll
        for (int ni = 0; ni < 8; ni++)
#pragma unroll
            for (int k = 0; k < 4; k++) sacc[ni][k] = 0.f;
#pragma unroll
        for (int kb = 0; kb < 8; kb++) {
            int k8 = kb * 8;
            float a[4];
            a[0] = Qs[m0 + g    ][k8 + q];
            a[1] = Qs[m0 + g + 8][k8 + q];
            a[2] = Qs[m0 + g    ][k8 + q + 4];
            a[3] = Qs[m0 + g + 8][k8 + q + 4];
#pragma unroll
            for (int ni = 0; ni < 8; ni++) {
                float bf[2];
                bf[0] = f2tf(Ks[s][ni * 8 + g][k8 + q]);
                bf[1] = f2tf(Ks[s][ni * 8 + g][k8 + q + 4]);
                mma8(sacc[ni], a, bf);
            }
        }

        // ---- online softmax (warp-local; rows g and g+8 of this warp) ----
#pragma unroll
        for (int ni = 0; ni < 8; ni++)
#pragma unroll
            for (int k = 0; k < 4; k++) sacc[ni][k] *= scale;

        float mx0 = -1e30f, mx1 = -1e30f;
#pragma unroll
        for (int ni = 0; ni < 8; ni++) {
            mx0 = fmaxf(mx0, fmaxf(sacc[ni][0], sacc[ni][1]));
            mx1 = fmaxf(mx1, fmaxf(sacc[ni][2], sacc[ni][3]));
        }
        mx0 = fmaxf(mx0, __shfl_xor_sync(0xffffffffu, mx0, 1));
        mx0 = fmaxf(mx0, __shfl_xor_sync(0xffffffffu, mx0, 2));
        mx1 = fmaxf(mx1, __shfl_xor_sync(0xffffffffu, mx1, 1));
        mx1 = fmaxf(mx1, __shfl_xor_sync(0xffffffffu, mx1, 2));

        float mn0 = fmaxf(mrow0, mx0), mn1 = fmaxf(mrow1, mx1);
        float corr0 = __expf(mrow0 - mn0), corr1 = __expf(mrow1 - mn1);
        mrow0 = mn0; mrow1 = mn1;

        __syncwarp();  // previous PV reads of Ps done before overwrite
        float ls0 = 0.f, ls1 = 0.f;
#pragma unroll
        for (int ni = 0; ni < 8; ni++) {
            float p0 = __expf(sacc[ni][0] - mn0);
            float p1 = __expf(sacc[ni][1] - mn0);
            float p2 = __expf(sacc[ni][2] - mn1);
            float p3 = __expf(sacc[ni][3] - mn1);
            ls0 += p0 + p1; ls1 += p2 + p3;
            int c = ni * 8 + q * 2;
            Ps[m0 + g    ][c] = f2tf(p0); Ps[m0 + g    ][c + 1] = f2tf(p1);
            Ps[m0 + g + 8][c] = f2tf(p2); Ps[m0 + g + 8][c + 1] = f2tf(p3);
        }
        lrow0 = lrow0 * corr0 + ls0;
        lrow1 = lrow1 * corr1 + ls1;
#pragma unroll
        for (int di = 0; di < 8; di++) {
            oacc[di][0] *= corr0; oacc[di][1] *= corr0;
            oacc[di][2] *= corr1; oacc[di][3] *= corr1;
        }
        __syncwarp();

        // ---- O += P V (this warp: 16x64 += 16x64 * 64x64) ----
#pragma unroll
        for (int kb = 0; kb < 8; kb++) {
            int k8 = kb * 8;
            float a[4];
            a[0] = Ps[m0 + g    ][k8 + q];
            a[1] = Ps[m0 + g + 8][k8 + q];
            a[2] = Ps[m0 + g    ][k8 + q + 4];
            a[3] = Ps[m0 + g + 8][k8 + q + 4];
#pragma unroll
            for (int di = 0; di < 8; di++) {
                float bf[2];
                bf[0] = f2tf(Vs[s][k8 + q    ][di * 8 + g]);
                bf[1] = f2tf(Vs[s][k8 + q + 4][di * 8 + g]);
                mma8(oacc[di], a, bf);
            }
        }
        __syncthreads();  // done with Ks[s]/Vs[s] before prefetch overwrites
    }

    // final row-sum reduction across the quad, then write O
    lrow0 += __shfl_xor_sync(0xffffffffu, lrow0, 1);
    lrow0 += __shfl_xor_sync(0xffffffffu, lrow0, 2);
    lrow1 += __shfl_xor_sync(0xffffffffu, lrow1, 1);
    lrow1 += __shfl_xor_sync(0xffffffffu, lrow1, 2);
    float inv0 = 1.f / lrow0, inv1 = 1.f / lrow1;

    int r0 = i0 + m0 + g, r1 = r0 + 8;
#pragma unroll
    for (int di = 0; di < 8; di++) {
        int c = h * DH_ + di * 8 + q * 2;
        size_t a0 = ((size_t)b * N_ + r0) * D_ + c;
        size_t a1 = ((size_t)b * N_ + r1) * D_ + c;
        *(float2*)(o + a0) = make_float2(oacc[di][0] * inv0, oacc[di][1] * inv0);
        *(float2*)(o + a1) = make_float2(oacc[di][2] * inv1, oacc[di][3] * inv1);
    }
}

// ---------------- orchestration --------------------------------------------
#define SMEM_BN256 ((2 * 128 * 36 + 2 * 32 * 260) * 4)
#define SMEM_BN128 ((2 * 128 * 36 + 2 * 32 * 132) * 4)

extern "C" void kernel_launch(void* const* d_in, const int* in_sizes, int n_in,
                              void* d_out, int out_size)
{
    (void)in_sizes; (void)n_in; (void)out_size;
    const float* x     = (const float*)d_in[0];
    const float* ln1_s = (const float*)d_in[1];
    const float* ln1_b = (const float*)d_in[2];
    const float* w_qkv = (const float*)d_in[3];
    const float* w_out = (const float*)d_in[4];
    const float* b_out = (const float*)d_in[5];
    const float* ln2_s = (const float*)d_in[6];
    const float* ln2_b = (const float*)d_in[7];
    const float* w1    = (const float*)d_in[8];
    const float* b1    = (const float*)d_in[9];
    const float* w2    = (const float*)d_in[10];
    const float* b2    = (const float*)d_in[11];
    float* out = (float*)d_out;

    float *h, *qkv, *o, *mlp;
    cudaGetSymbolAddress((void**)&h,    g_h);
    cudaGetSymbolAddress((void**)&qkv,  g_qkv);
    cudaGetSymbolAddress((void**)&o,    g_o);
    cudaGetSymbolAddress((void**)&mlp,  g_mlp);

    cudaFuncSetAttribute(gemm_tc<256, 64, 64, 0>,
        cudaFuncAttributeMaxDynamicSharedMemorySize, SMEM_BN256);
    cudaFuncSetAttribute(gemm_tc<256, 64, 64, 3>,
        cudaFuncAttributeMaxDynamicSharedMemorySize, SMEM_BN256);
    cudaFuncSetAttribute(gemm_tc<128, 32, 64, 5>,
        cudaFuncAttributeMaxDynamicSharedMemorySize, SMEM_BN128);
    cudaFuncSetAttribute(flash_tc,
        cudaFuncAttributeMaxDynamicSharedMemorySize, FSMEM);

    cudaMemcpyAsync(out, x, (size_t)M_ * D_ * sizeof(float),
                    cudaMemcpyDeviceToDevice);

    for (int l = 0; l < DEPTH_; l++) {
        // --- attention block ---
        ln_kernel<<<M_, 256>>>(out, ln1_s + (size_t)l * D_, ln1_b + (size_t)l * D_, h);
        gemm_tc<256, 64, 64, 0><<<dim3(3 * D_ / 256, M_ / 128), 256, SMEM_BN256>>>(
            h, w_qkv + (size_t)l * D_ * 3 * D_, nullptr, nullptr,
            qkv, M_, 3 * D_, D_);
        flash_tc<<<dim3(N_ / 128, B_ * H_), 256, FSMEM>>>(qkv, o);
        gemm_tc<128, 32, 64, 5><<<dim3(D_ / 128, M_ / 128), 256, SMEM_BN128>>>(
            o, w_out + (size_t)l * D_ * D_, b_out + (size_t)l * D_,
            out, out, M_, D_, D_);
        // --- MLP block ---
        ln_kernel<<<M_, 256>>>(out, ln2_s + (size_t)l * D_, ln2_b + (size_t)l * D_, h);
        gemm_tc<256, 64, 64, 3><<<dim3(MLP_ / 256, M_ / 128), 256, SMEM_BN256>>>(
            h, w1 + (size_t)l * D_ * MLP_, b1 + (size_t)l * MLP_,
            nullptr, mlp, M_, MLP_, D_);
        gemm_tc<128, 32, 64, 5><<<dim3(D_ / 128, M_ / 128), 256, SMEM_BN128>>>(
            mlp, w2 + (size_t)l * MLP_ * D_, b2 + (size_t)l * D_,
            out, out, M_, D_, MLP_);
    }
}

// round 5
// speedup vs baseline: 1.3546x; 1.3546x over previous
#include <cuda_runtime.h>
#include <math.h>
#include <stdint.h>

#define B_    2
#define N_    1024
#define D_    1024
#define H_    16
#define DH_   64
#define MLP_  4096
#define DEPTH_ 6
#define M_    (B_ * N_)   /* 2048 rows */

// ---------------- scratch -----------------------------------------------
__device__ float g_h   [(size_t)M_ * D_];
__device__ float g_qkv [(size_t)M_ * 3 * D_];
__device__ float g_attn[(size_t)B_ * H_ * N_ * N_];
__device__ float g_o   [(size_t)M_ * D_];
__device__ float g_mlp [(size_t)M_ * MLP_];
// pre-rounded (tf32-RNA) weight copies
__device__ float g_wqkv[(size_t)DEPTH_ * D_ * 3 * D_];
__device__ float g_wout[(size_t)DEPTH_ * D_ * D_];
__device__ float g_w1  [(size_t)DEPTH_ * D_ * MLP_];
__device__ float g_w2  [(size_t)DEPTH_ * MLP_ * D_];

// ---------------- tf32 / async helpers ------------------------------------
__device__ __forceinline__ float f2tf(float x) {
    uint32_t u; asm("cvt.rna.tf32.f32 %0, %1;" : "=r"(u) : "f"(x));
    return __uint_as_float(u);
}
__device__ __forceinline__ void mma8(float* d, const float* a, const float* b) {
    asm volatile(
        "mma.sync.aligned.m16n8k8.row.col.f32.tf32.tf32.f32 "
        "{%0,%1,%2,%3},{%4,%5,%6,%7},{%8,%9},{%0,%1,%2,%3};"
        : "+f"(d[0]), "+f"(d[1]), "+f"(d[2]), "+f"(d[3])
        : "r"(__float_as_uint(a[0])), "r"(__float_as_uint(a[1])),
          "r"(__float_as_uint(a[2])), "r"(__float_as_uint(a[3])),
          "r"(__float_as_uint(b[0])), "r"(__float_as_uint(b[1])));
}
__device__ __forceinline__ void cp16(void* smem_dst, const void* gmem_src) {
    uint32_t dst = (uint32_t)__cvta_generic_to_shared(smem_dst);
    asm volatile("cp.async.cg.shared.global [%0], [%1], 16;"
                 :: "r"(dst), "l"(gmem_src));
}
__device__ __forceinline__ void cp_commit() {
    asm volatile("cp.async.commit_group;");
}

// ---------------- weight pre-rounding (fp32 -> tf32-RNA bits) --------------
__global__ void __launch_bounds__(256) tf32_round_kernel(
    const float4* __restrict__ src, float4* __restrict__ dst, int n4)
{
    int stride = gridDim.x * blockDim.x;
    for (int i = blockIdx.x * blockDim.x + threadIdx.x; i < n4; i += stride) {
        float4 f = src[i];
        f.x = f2tf(f.x); f.y = f2tf(f.y); f.z = f2tf(f.z); f.w = f2tf(f.w);
        dst[i] = f;
    }
}

// ---------------- LayerNorm (emits tf32-rounded values) --------------------
__global__ void __launch_bounds__(256) ln_kernel(
    const float* __restrict__ x, const float* __restrict__ s,
    const float* __restrict__ b, float* __restrict__ o)
{
    __shared__ float red[2][8];
    int row = blockIdx.x;
    const float* xr = x + (size_t)row * D_;
    float* orow = o + (size_t)row * D_;
    int t = threadIdx.x;
    float v[4];
    float sum = 0.f, sq = 0.f;
#pragma unroll
    for (int i = 0; i < 4; i++) {
        float z = xr[t + i * 256];
        v[i] = z; sum += z; sq += z * z;
    }
#pragma unroll
    for (int off = 16; off > 0; off >>= 1) {
        sum += __shfl_xor_sync(0xffffffffu, sum, off);
        sq  += __shfl_xor_sync(0xffffffffu, sq,  off);
    }
    if ((t & 31) == 0) { red[0][t >> 5] = sum; red[1][t >> 5] = sq; }
    __syncthreads();
    sum = 0.f; sq = 0.f;
#pragma unroll
    for (int i = 0; i < 8; i++) { sum += red[0][i]; sq += red[1][i]; }
    float mean = sum * (1.f / D_);
    float var  = sq  * (1.f / D_) - mean * mean;
    float rstd = rsqrtf(var + 1e-5f);
#pragma unroll
    for (int i = 0; i < 4; i++) {
        int c = t + i * 256;
        orow[c] = f2tf((v[i] - mean) * rstd * s[c] + b[c]);
    }
}

// ---------------- tf32 tensor-core GEMM, 3-stage cp.async pipeline ---------
// Inputs assumed already tf32-rounded. EPI bit0:+bias bit1:gelu bit2:+res.
// ROUND: round outputs to tf32 (for buffers feeding a later GEMM A operand).
template<int BN, int WM, int WN, int EPI, int ROUND>
__global__ void __launch_bounds__(256, 1) gemm_tc(
    const float* __restrict__ A, const float* __restrict__ W,
    const float* __restrict__ bias, const float* __restrict__ res,
    float* __restrict__ C, int M, int N, int K)
{
    const int BNP = BN + 4;
    const int MI = WM / 16, NI = WN / 8;
    const int WARPS_N = BN / WN;

    extern __shared__ float sm[];
    float (*As)[128][36] = reinterpret_cast<float(*)[128][36]>(sm);
    float (*Bs)[32][BNP] = reinterpret_cast<float(*)[32][BNP]>(sm + 3 * 128 * 36);

    int tid = threadIdx.x;
    int bx = blockIdx.x, by = blockIdx.y;
    int w = tid >> 5, lane = tid & 31;
    int wn = w % WARPS_N, wm = w / WARPS_N;
    int g = lane >> 2, q = lane & 3;

    const float* Ab = A + (size_t)by * 128 * K;
    const float* Wb = W + (size_t)bx * BN;
    int KT = K / 32;

    float acc[MI][NI][4];
#pragma unroll
    for (int mi = 0; mi < MI; mi++)
#pragma unroll
        for (int ni = 0; ni < NI; ni++)
#pragma unroll
            for (int k = 0; k < 4; k++) acc[mi][ni][k] = 0.f;

    auto load_tile = [&](int kt, int s) {
        int k0 = kt * 32;
#pragma unroll
        for (int i = 0; i < 4; i++) {
            int idx = tid + i * 256;
            int r = idx >> 3, c4 = (idx & 7) * 4;
            cp16(&As[s][r][c4], Ab + (size_t)r * K + k0 + c4);
        }
#pragma unroll
        for (int i = 0; i < BN / 32; i++) {
            int idx = tid + i * 256;
            int r = idx / (BN / 4), c4 = (idx % (BN / 4)) * 4;
            cp16(&Bs[s][r][c4], Wb + (size_t)(k0 + r) * N + c4);
        }
        cp_commit();
    };

    load_tile(0, 0);
    load_tile(1, 1);

    for (int kt = 0; kt < KT; kt++) {
        asm volatile("cp.async.wait_group 1;");
        __syncthreads();
        if (kt + 2 < KT) load_tile(kt + 2, (kt + 2) % 3);
        else cp_commit();   // keep group count advancing for the tail
        int s = kt % 3;
#pragma unroll
        for (int ks = 0; ks < 4; ks++) {
            int kb = ks * 8;
            float a[MI][4];
#pragma unroll
            for (int mi = 0; mi < MI; mi++) {
                int m = wm * WM + mi * 16;
                a[mi][0] = As[s][m + g    ][kb + q];
                a[mi][1] = As[s][m + g + 8][kb + q];
                a[mi][2] = As[s][m + g    ][kb + q + 4];
                a[mi][3] = As[s][m + g + 8][kb + q + 4];
            }
            float b[NI][2];
#pragma unroll
            for (int ni = 0; ni < NI; ni++) {
                int n = wn * WN + ni * 8 + g;
                b[ni][0] = Bs[s][kb + q    ][n];
                b[ni][1] = Bs[s][kb + q + 4][n];
            }
#pragma unroll
            for (int mi = 0; mi < MI; mi++)
#pragma unroll
                for (int ni = 0; ni < NI; ni++) mma8(acc[mi][ni], a[mi], b[ni]);
        }
    }

#pragma unroll
    for (int mi = 0; mi < MI; mi++) {
        int r0 = by * 128 + wm * WM + mi * 16 + g;
#pragma unroll
        for (int ni = 0; ni < NI; ni++) {
            int c = bx * BN + wn * WN + ni * 8 + q * 2;
            float2 v0 = make_float2(acc[mi][ni][0], acc[mi][ni][1]);
            float2 v1 = make_float2(acc[mi][ni][2], acc[mi][ni][3]);
            if (EPI & 1) {
                float b0 = bias[c], b1 = bias[c + 1];
                v0.x += b0; v0.y += b1; v1.x += b0; v1.y += b1;
            }
            if (EPI & 2) {
                const float is2 = 0.70710678118654752f;
                v0.x = 0.5f * v0.x * (1.f + erff(v0.x * is2));
                v0.y = 0.5f * v0.y * (1.f + erff(v0.y * is2));
                v1.x = 0.5f * v1.x * (1.f + erff(v1.x * is2));
                v1.y = 0.5f * v1.y * (1.f + erff(v1.y * is2));
            }
            size_t a0 = (size_t)r0 * N + c;
            size_t a1 = (size_t)(r0 + 8) * N + c;
            if (EPI & 4) {
                float2 r0v = *(const float2*)(res + a0);
                float2 r1v = *(const float2*)(res + a1);
                v0.x += r0v.x; v0.y += r0v.y; v1.x += r1v.x; v1.y += r1v.y;
            }
            if (ROUND) {
                v0.x = f2tf(v0.x); v0.y = f2tf(v0.y);
                v1.x = f2tf(v1.x); v1.y = f2tf(v1.y);
            }
            *(float2*)(C + a0) = v0;
            *(float2*)(C + a1) = v1;
        }
    }
}

// ---------------- attention scores: S = Q K^T * scale (tf32 TC) -----------
__global__ void __launch_bounds__(256) scores_tc(
    const float* __restrict__ qkv, float* __restrict__ attn)
{
    __shared__ float Qs[128][36];
    __shared__ float Ks[128][36];
    int bh = blockIdx.z;
    int b = bh >> 4, h = bh & 15;
    int i0 = blockIdx.y * 128, j0 = blockIdx.x * 128;
    const float* Qb = qkv + (size_t)b * N_ * 3 * D_ + (size_t)h * DH_;
    const float* Kb = Qb + D_;
    int tid = threadIdx.x;
    int w = tid >> 5, lane = tid & 31;
    int wm = w >> 1, wn = w & 1;
    int g = lane >> 2, q = lane & 3;

    float acc[2][8][4];
#pragma unroll
    for (int mi = 0; mi < 2; mi++)
#pragma unroll
        for (int ni = 0; ni < 8; ni++)
#pragma unroll
            for (int k = 0; k < 4; k++) acc[mi][ni][k] = 0.f;

#pragma unroll
    for (int k0 = 0; k0 < 64; k0 += 32) {
#pragma unroll
        for (int i = 0; i < 4; i++) {
            int idx = tid + i * 256;
            int r = idx >> 3, c4 = (idx & 7) * 4;
            float4 fq = *(const float4*)(Qb + (size_t)(i0 + r) * 3 * D_ + k0 + c4);
            fq.x = f2tf(fq.x); fq.y = f2tf(fq.y); fq.z = f2tf(fq.z); fq.w = f2tf(fq.w);
            *(float4*)&Qs[r][c4] = fq;
            float4 fk = *(const float4*)(Kb + (size_t)(j0 + r) * 3 * D_ + k0 + c4);
            fk.x = f2tf(fk.x); fk.y = f2tf(fk.y); fk.z = f2tf(fk.z); fk.w = f2tf(fk.w);
            *(float4*)&Ks[r][c4] = fk;
        }
        __syncthreads();
#pragma unroll
        for (int ks = 0; ks < 4; ks++) {
            int kb = ks * 8;
            float a[2][4];
#pragma unroll
            for (int mi = 0; mi < 2; mi++) {
                int m = wm * 32 + mi * 16;
                a[mi][0] = Qs[m + g    ][kb + q];
                a[mi][1] = Qs[m + g + 8][kb + q];
                a[mi][2] = Qs[m + g    ][kb + q + 4];
                a[mi][3] = Qs[m + g + 8][kb + q + 4];
            }
            float bf[8][2];
#pragma unroll
            for (int ni = 0; ni < 8; ni++) {
                int n = wn * 64 + ni * 8 + g;
                bf[ni][0] = Ks[n][kb + q];
                bf[ni][1] = Ks[n][kb + q + 4];
            }
#pragma unroll
            for (int mi = 0; mi < 2; mi++)
#pragma unroll
                for (int ni = 0; ni < 8; ni++) mma8(acc[mi][ni], a[mi], bf[ni]);
        }
        __syncthreads();
    }

    const float scale = 0.03125f;
#pragma unroll
    for (int mi = 0; mi < 2; mi++) {
        int r0 = i0 + wm * 32 + mi * 16 + g;
#pragma unroll
        for (int ni = 0; ni < 8; ni++) {
            int c = j0 + wn * 64 + ni * 8 + q * 2;
            size_t a0 = ((size_t)bh * N_ + r0) * N_ + c;
            size_t a1 = ((size_t)bh * N_ + r0 + 8) * N_ + c;
            *(float2*)(attn + a0) =
                make_float2(acc[mi][ni][0] * scale, acc[mi][ni][1] * scale);
            *(float2*)(attn + a1) =
                make_float2(acc[mi][ni][2] * scale, acc[mi][ni][3] * scale);
        }
    }
}

// ---------------- row softmax over N=1024 ----------------------------------
__global__ void __launch_bounds__(256) softmax_kernel(float* __restrict__ attn)
{
    __shared__ float red[8];
    size_t row = blockIdx.x;
    float* p = attn + row * N_;
    int t = threadIdx.x;
    float v[4];
    float mx = -1e30f;
#pragma unroll
    for (int i = 0; i < 4; i++) { v[i] = p[t + i * 256]; mx = fmaxf(mx, v[i]); }
#pragma unroll
    for (int off = 16; off > 0; off >>= 1)
        mx = fmaxf(mx, __shfl_xor_sync(0xffffffffu, mx, off));
    if ((t & 31) == 0) red[t >> 5] = mx;
    __syncthreads();
    mx = red[0];
#pragma unroll
    for (int i = 1; i < 8; i++) mx = fmaxf(mx, red[i]);
    __syncthreads();
    float sum = 0.f;
#pragma unroll
    for (int i = 0; i < 4; i++) { v[i] = __expf(v[i] - mx); sum += v[i]; }
#pragma unroll
    for (int off = 16; off > 0; off >>= 1)
        sum += __shfl_xor_sync(0xffffffffu, sum, off);
    if ((t & 31) == 0) red[t >> 5] = sum;
    __syncthreads();
    sum = 0.f;
#pragma unroll
    for (int i = 0; i < 8; i++) sum += red[i];
    float inv = 1.f / sum;
#pragma unroll
    for (int i = 0; i < 4; i++) p[t + i * 256] = v[i] * inv;
}

// ---------------- O = attn @ V (tf32 TC), output [b, n, h*dh], rounded -----
__global__ void __launch_bounds__(256) av_tc(
    const float* __restrict__ attn, const float* __restrict__ qkv,
    float* __restrict__ o)
{
    __shared__ float As_[128][36];
    __shared__ float Vs[32][68];
    int bh = blockIdx.y;
    int b = bh >> 4, h = bh & 15;
    int i0 = blockIdx.x * 128;
    const float* Ab = attn + ((size_t)bh * N_ + i0) * N_;
    const float* Vb = qkv + (size_t)b * N_ * 3 * D_ + 2 * D_ + (size_t)h * DH_;
    int tid = threadIdx.x;
    int w = tid >> 5, lane = tid & 31;
    int wm = w >> 1, wn = w & 1;
    int g = lane >> 2, q = lane & 3;

    float acc[2][4][4];
#pragma unroll
    for (int mi = 0; mi < 2; mi++)
#pragma unroll
        for (int ni = 0; ni < 4; ni++)
#pragma unroll
            for (int k = 0; k < 4; k++) acc[mi][ni][k] = 0.f;

    for (int k0 = 0; k0 < N_; k0 += 32) {
#pragma unroll
        for (int i = 0; i < 4; i++) {
            int idx = tid + i * 256;
            int r = idx >> 3, c4 = (idx & 7) * 4;
            float4 f = *(const float4*)(Ab + (size_t)r * N_ + k0 + c4);
            f.x = f2tf(f.x); f.y = f2tf(f.y); f.z = f2tf(f.z); f.w = f2tf(f.w);
            *(float4*)&As_[r][c4] = f;
        }
#pragma unroll
        for (int i = 0; i < 2; i++) {
            int idx = tid + i * 256;
            int r = idx >> 4, c4 = (idx & 15) * 4;
            float4 f = *(const float4*)(Vb + (size_t)(k0 + r) * 3 * D_ + c4);
            f.x = f2tf(f.x); f.y = f2tf(f.y); f.z = f2tf(f.z); f.w = f2tf(f.w);
            *(float4*)&Vs[r][c4] = f;
        }
        __syncthreads();
#pragma unroll
        for (int ks = 0; ks < 4; ks++) {
            int kb = ks * 8;
            float a[2][4];
#pragma unroll
            for (int mi = 0; mi < 2; mi++) {
                int m = wm * 32 + mi * 16;
                a[mi][0] = As_[m + g    ][kb + q];
                a[mi][1] = As_[m + g + 8][kb + q];
                a[mi][2] = As_[m + g    ][kb + q + 4];
                a[mi][3] = As_[m + g + 8][kb + q + 4];
            }
            float bf[4][2];
#pragma unroll
            for (int ni = 0; ni < 4; ni++) {
                int n = wn * 32 + ni * 8 + g;
                bf[ni][0] = Vs[kb + q    ][n];
                bf[ni][1] = Vs[kb + q + 4][n];
            }
#pragma unroll
            for (int mi = 0; mi < 2; mi++)
#pragma unroll
                for (int ni = 0; ni < 4; ni++) mma8(acc[mi][ni], a[mi], bf[ni]);
        }
        __syncthreads();
    }

#pragma unroll
    for (int mi = 0; mi < 2; mi++) {
        int r0 = i0 + wm * 32 + mi * 16 + g;
#pragma unroll
        for (int ni = 0; ni < 4; ni++) {
            int c = wn * 32 + ni * 8 + q * 2;
            size_t a0 = ((size_t)b * N_ + r0) * D_ + h * DH_ + c;
            size_t a1 = ((size_t)b * N_ + r0 + 8) * D_ + h * DH_ + c;
            *(float2*)(o + a0) = make_float2(f2tf(acc[mi][ni][0]), f2tf(acc[mi][ni][1]));
            *(float2*)(o + a1) = make_float2(f2tf(acc[mi][ni][2]), f2tf(acc[mi][ni][3]));
        }
    }
}

// ---------------- orchestration --------------------------------------------
#define SMEM3_BN256 ((3 * 128 * 36 + 3 * 32 * 260) * 4)
#define SMEM3_BN128 ((3 * 128 * 36 + 3 * 32 * 132) * 4)

extern "C" void kernel_launch(void* const* d_in, const int* in_sizes, int n_in,
                              void* d_out, int out_size)
{
    (void)in_sizes; (void)n_in; (void)out_size;
    const float* x     = (const float*)d_in[0];
    const float* ln1_s = (const float*)d_in[1];
    const float* ln1_b = (const float*)d_in[2];
    const float* w_qkv = (const float*)d_in[3];
    const float* w_out = (const float*)d_in[4];
    const float* b_out = (const float*)d_in[5];
    const float* ln2_s = (const float*)d_in[6];
    const float* ln2_b = (const float*)d_in[7];
    const float* w1    = (const float*)d_in[8];
    const float* b1    = (const float*)d_in[9];
    const float* w2    = (const float*)d_in[10];
    const float* b2    = (const float*)d_in[11];
    float* out = (float*)d_out;

    float *h, *qkv, *attn, *o, *mlp, *wqkv, *wout, *w1r, *w2r;
    cudaGetSymbolAddress((void**)&h,    g_h);
    cudaGetSymbolAddress((void**)&qkv,  g_qkv);
    cudaGetSymbolAddress((void**)&attn, g_attn);
    cudaGetSymbolAddress((void**)&o,    g_o);
    cudaGetSymbolAddress((void**)&mlp,  g_mlp);
    cudaGetSymbolAddress((void**)&wqkv, g_wqkv);
    cudaGetSymbolAddress((void**)&wout, g_wout);
    cudaGetSymbolAddress((void**)&w1r,  g_w1);
    cudaGetSymbolAddress((void**)&w2r,  g_w2);

    cudaFuncSetAttribute(gemm_tc<256, 64, 64, 0, 0>,
        cudaFuncAttributeMaxDynamicSharedMemorySize, SMEM3_BN256);
    cudaFuncSetAttribute(gemm_tc<256, 64, 64, 3, 1>,
        cudaFuncAttributeMaxDynamicSharedMemorySize, SMEM3_BN256);
    cudaFuncSetAttribute(gemm_tc<128, 32, 64, 5, 0>,
        cudaFuncAttributeMaxDynamicSharedMemorySize, SMEM3_BN128);

    // pre-round all weights to tf32 (RNA) into scratch
    tf32_round_kernel<<<2048, 256>>>((const float4*)w_qkv, (float4*)wqkv,
        (int)((size_t)DEPTH_ * D_ * 3 * D_ / 4));
    tf32_round_kernel<<<2048, 256>>>((const float4*)w_out, (float4*)wout,
        (int)((size_t)DEPTH_ * D_ * D_ / 4));
    tf32_round_kernel<<<2048, 256>>>((const float4*)w1, (float4*)w1r,
        (int)((size_t)DEPTH_ * D_ * MLP_ / 4));
    tf32_round_kernel<<<2048, 256>>>((const float4*)w2, (float4*)w2r,
        (int)((size_t)DEPTH_ * MLP_ * D_ / 4));

    cudaMemcpyAsync(out, x, (size_t)M_ * D_ * sizeof(float),
                    cudaMemcpyDeviceToDevice);

    for (int l = 0; l < DEPTH_; l++) {
        // --- attention block ---
        ln_kernel<<<M_, 256>>>(out, ln1_s + (size_t)l * D_, ln1_b + (size_t)l * D_, h);
        gemm_tc<256, 64, 64, 0, 0><<<dim3(3 * D_ / 256, M_ / 128), 256, SMEM3_BN256>>>(
            h, wqkv + (size_t)l * D_ * 3 * D_, nullptr, nullptr,
            qkv, M_, 3 * D_, D_);
        scores_tc<<<dim3(8, 8, B_ * H_), 256>>>(qkv, attn);
        softmax_kernel<<<B_ * H_ * N_, 256>>>(attn);
        av_tc<<<dim3(8, B_ * H_), 256>>>(attn, qkv, o);
        gemm_tc<128, 32, 64, 5, 0><<<dim3(D_ / 128, M_ / 128), 256, SMEM3_BN128>>>(
            o, wout + (size_t)l * D_ * D_, b_out + (size_t)l * D_,
            out, out, M_, D_, D_);
        // --- MLP block ---
        ln_kernel<<<M_, 256>>>(out, ln2_s + (size_t)l * D_, ln2_b + (size_t)l * D_, h);
        gemm_tc<256, 64, 64, 3, 1><<<dim3(MLP_ / 256, M_ / 128), 256, SMEM3_BN256>>>(
            h, w1r + (size_t)l * D_ * MLP_, b1 + (size_t)l * MLP_,
            nullptr, mlp, M_, MLP_, D_);
        gemm_tc<128, 32, 64, 5, 0><<<dim3(D_ / 128, M_ / 128), 256, SMEM3_BN128>>>(
            mlp, w2r + (size_t)l * MLP_ * D_, b2 + (size_t)l * D_,
            out, out, M_, D_, MLP_);
    }
}